// round 13
// baseline (speedup 1.0000x reference)
#include <cuda_runtime.h>
#include <math.h>

#define B_    128
#define NP_   256
#define NN    (B_*NP_)
#define H_    128
#define DIMS_ 128
#define HEADS_ 8
#define DK_   16
#define C1_   32
#define C2_   64
#define NC_   10
#define EPG   4096
#define ETOT  (B_*EPG)
#define PPAD  132
#define SSTR  129

// ------------------- device scratch -------------------
__device__ float g_deg[NN];
__device__ float g_dnorm[NN];
__device__ int   g_off[NN];
__device__ int   g_cur[NN];
__device__ unsigned short g_csr[ETOT];
__device__ float g_h0[(size_t)NN*H_];
__device__ float g_h1[(size_t)NN*H_];
__device__ float g_score[(size_t)3*NN];
__device__ float g_feats[(size_t)3*B_*DIMS_*H_];
__device__ float g_qkv[(size_t)B_*DIMS_*384];
__device__ float g_Wqkv[(size_t)H_*384];

// ------------------- side stream + events -------------------
static cudaStream_t s_side = 0;
static cudaEvent_t  s_evL[3] = {0,0,0};
static cudaEvent_t  s_evG[3] = {0,0,0};
static cudaEvent_t  s_evJoin = 0;
static void ensure_streams() {
    if (!s_side) {
        cudaStreamCreateWithFlags(&s_side, cudaStreamNonBlocking);
        for (int i = 0; i < 3; i++) {
            cudaEventCreateWithFlags(&s_evL[i], cudaEventDisableTiming);
            cudaEventCreateWithFlags(&s_evG[i], cudaEventDisableTiming);
        }
        cudaEventCreateWithFlags(&s_evJoin, cudaEventDisableTiming);
    }
}
namespace { struct _StreamInit { _StreamInit() { ensure_streams(); } } _stream_init; }

// ------------------- prep -------------------
__global__ void zero_kernel() {
    int i = blockIdx.x * blockDim.x + threadIdx.x;
    if (i < NN) { g_deg[i] = 0.f; g_cur[i] = 0; }
}
__global__ void deg_kernel(const int* __restrict__ dst, int E) {
    int e = blockIdx.x * blockDim.x + threadIdx.x;
    if (e < E) atomicAdd(&g_deg[dst[e]], 1.0f);
}
__global__ void scan_kernel() {
    int g = blockIdx.x, t = threadIdx.x;
    __shared__ int a[NP_];
    int node = g*NP_ + t;
    float degf = g_deg[node];
    int v = (int)degf;
    a[t] = v;
    __syncthreads();
    for (int off = 1; off < NP_; off <<= 1) {
        int x = a[t];
        if (t >= off) x += a[t - off];
        __syncthreads();
        a[t] = x;
        __syncthreads();
    }
    g_off[node] = g*EPG + a[t] - v;
    g_dnorm[node] = rsqrtf(fmaxf(degf, 1.0f));
}
__global__ void scatter_kernel(const int* __restrict__ src, const int* __restrict__ dst, int E,
                               const float* __restrict__ Wq, const float* __restrict__ Wk,
                               const float* __restrict__ Wv) {
    int e = blockIdx.x * blockDim.x + threadIdx.x;
    if (e < E) {
        int s = src[e], d = dst[e];
        int pos = atomicAdd(&g_cur[d], 1);
        g_csr[g_off[d] + pos] = (unsigned short)(s & 255);
    }
    if (e < H_*H_) {
        int k = e >> 7, c = e & 127;
        g_Wqkv[k*384 + c]       = Wq[e];
        g_Wqkv[k*384 + 128 + c] = Wk[e];
        g_Wqkv[k*384 + 256 + c] = Wv[e];
    }
}

// ------------------- mega-fused layer kernel (phases 1-4 only; scores -> global) -------------------
__global__ void __launch_bounds__(1024, 1)
layer_kernel(const float* __restrict__ hin, const float* __restrict__ W,
             const float* __restrict__ bias, const float* __restrict__ Wp,
             const float* __restrict__ bp, float* __restrict__ hout, int layer)
{
    extern __shared__ float sm[];
    float* P    = sm;                      // [256][132]
    float* Wm   = P + 256*PPAD;            // [128][128]
    float* dn   = Wm + 128*128;            // [256]
    float* sps  = dn + 256;                // [256]
    float* ssh  = sps + 256;               // [256]

    int g = blockIdx.x, t = threadIdx.x;   // 1024 threads

    // ---- phase 1: stage ----
    for (int i = t; i < 128*32; i += 1024)
        ((float4*)Wm)[i] = ((const float4*)W)[i];
    if (t < 256) dn[t] = g_dnorm[g*NP_ + t];
    {
        const float4* h4 = (const float4*)(hin + (size_t)g*NP_*H_);
        for (int i = t; i < 256*32; i += 1024) {
            int r = i >> 5, c = i & 31;
            *(float4*)&P[r*PPAD + c*4] = h4[i];
        }
    }
    __syncthreads();

    // ---- phase 2: in-place GEMM pre = h @ W (1 row x 32 cols per thread) ----
    {
        int r = t & 255, cg = t >> 8;      // 256 rows x 4 col-groups
        int c0 = cg * 32;
        float acc[32];
        #pragma unroll
        for (int j = 0; j < 32; j++) acc[j] = 0.f;
        const float* arow = &P[r*PPAD];
        for (int k = 0; k < 128; k++) {
            float a = arow[k];
            const float4* wr4 = (const float4*)(Wm + k*128 + c0);
            #pragma unroll
            for (int j4 = 0; j4 < 8; j4++) {
                float4 w4 = wr4[j4];
                acc[j4*4+0] += a * w4.x;
                acc[j4*4+1] += a * w4.y;
                acc[j4*4+2] += a * w4.z;
                acc[j4*4+3] += a * w4.w;
            }
        }
        __syncthreads();   // all reads of h done before overwrite
        float sc = dn[r];
        float4* prow4 = (float4*)(P + r*PPAD + c0);
        #pragma unroll
        for (int j4 = 0; j4 < 8; j4++)
            prow4[j4] = make_float4(acc[j4*4+0]*sc, acc[j4*4+1]*sc,
                                    acc[j4*4+2]*sc, acc[j4*4+3]*sc);
    }
    __syncthreads();

    // ---- phase 3: CSR aggregation + relu + bias, fused sp projection ----
    {
        int warp = t >> 5, lane = t & 31;   // 32 warps x 8 nodes
        float4 bv = ((const float4*)bias)[lane];
        float4 wp = ((const float4*)Wp)[lane];
        for (int d0 = warp*8; d0 < warp*8 + 8; d0 += 4) {
            int beg[4], len[4];
            float4 acc[4];
            int maxlen = 0;
            #pragma unroll
            for (int j = 0; j < 4; j++) {
                int node = g*NP_ + d0 + j;
                beg[j] = g_off[node];
                len[j] = (int)g_deg[node];
                maxlen = max(maxlen, len[j]);
                acc[j] = make_float4(0.f, 0.f, 0.f, 0.f);
            }
            for (int i = 0; i < maxlen; i++) {
                #pragma unroll
                for (int j = 0; j < 4; j++) {
                    if (i < len[j]) {
                        int s = g_csr[beg[j] + i];
                        float4 vv = *(const float4*)&P[s*PPAD + lane*4];
                        acc[j].x += vv.x; acc[j].y += vv.y; acc[j].z += vv.z; acc[j].w += vv.w;
                    }
                }
            }
            #pragma unroll
            for (int j = 0; j < 4; j++) {
                int node = g*NP_ + d0 + j;
                float sc = dn[d0 + j];
                float4 o;
                o.x = fmaxf(acc[j].x*sc + bv.x, 0.f);
                o.y = fmaxf(acc[j].y*sc + bv.y, 0.f);
                o.z = fmaxf(acc[j].z*sc + bv.z, 0.f);
                o.w = fmaxf(acc[j].w*sc + bv.w, 0.f);
                ((float4*)hout)[(size_t)node*32 + lane] = o;
                float s = o.x*wp.x + o.y*wp.y + o.z*wp.z + o.w*wp.w;
                #pragma unroll
                for (int off = 16; off; off >>= 1) s += __shfl_down_sync(0xffffffffu, s, off);
                if (lane == 0) sps[d0 + j] = s;
            }
        }
    }
    __syncthreads();

    // ---- phase 4: score via CSR -> global per-layer buffer ----
    if (t < 256) ssh[t] = sps[t] * dn[t];
    __syncthreads();
    if (t < 256) {
        int node = g*NP_ + t;
        int beg = g_off[node], len = (int)g_deg[node];
        float s = 0.f;
        for (int i = 0; i < len; i++) s += ssh[g_csr[beg + i]];
        g_score[(size_t)layer*NN + node] = s * dn[t] + bp[0];
    }
}

// ------------------- sort (bitonic, desc value / asc index) + gather + gate -------------------
__global__ void sortgather_kernel(const float* __restrict__ hsrc, int layer) {
    __shared__ float v[NP_];
    __shared__ int   ix[NP_];
    __shared__ float gate[DIMS_];
    int g = blockIdx.x, t = threadIdx.x;   // 256 threads
    v[t]  = g_score[(size_t)layer*NN + g*NP_ + t];
    ix[t] = t;
    __syncthreads();
    for (int k = 2; k <= NP_; k <<= 1) {
        for (int j = k >> 1; j > 0; j >>= 1) {
            int p = t ^ j;
            if (p > t) {
                bool dirDesc = ((t & k) == 0);
                float v1 = v[t], v2 = v[p];
                int i1 = ix[t], i2 = ix[p];
                bool a_gt = (v1 > v2) || (v1 == v2 && i1 < i2);
                if (dirDesc != a_gt) {
                    v[t] = v2; v[p] = v1; ix[t] = i2; ix[p] = i1;
                }
            }
            __syncthreads();
        }
    }
    if (t < DIMS_) gate[t] = tanhf(v[t]);
    __syncthreads();
    float* dstp = g_feats + (size_t)(layer*B_ + g)*DIMS_*H_;
    for (int e = t; e < DIMS_*H_; e += 256) {
        int j = e >> 7, c = e & 127;
        dstp[e] = hsrc[((size_t)g*NP_ + ix[j])*H_ + c] * gate[j];
    }
}

// ------------------- fp32 SGEMM (QKV): 128x128 tile, 8x8/thread -------------------
__global__ void gemm128(const float* __restrict__ A, const float* __restrict__ B,
                        float* __restrict__ C, int M, int Nn, int K)
{
    __shared__ float As[8][128];
    __shared__ float Bs[8][128];
    int t = threadIdx.x;
    int m0 = blockIdx.x * 128, n0 = blockIdx.y * 128;
    int tx = t & 15, ty = t >> 4;
    int arow = t >> 1, aseg = t & 1;
    int brow = t >> 5, bcol = t & 31;
    float acc[8][8];
    #pragma unroll
    for (int i = 0; i < 8; i++)
        #pragma unroll
        for (int j = 0; j < 8; j++) acc[i][j] = 0.f;

    for (int k0 = 0; k0 < K; k0 += 8) {
        float4 av  = *(const float4*)(A + (size_t)(m0 + arow)*K + k0 + aseg*4);
        float4 bvv = *(const float4*)(B + (size_t)(k0 + brow)*Nn + n0 + bcol*4);
        As[aseg*4+0][arow] = av.x;
        As[aseg*4+1][arow] = av.y;
        As[aseg*4+2][arow] = av.z;
        As[aseg*4+3][arow] = av.w;
        *(float4*)&Bs[brow][bcol*4] = bvv;
        __syncthreads();
        #pragma unroll
        for (int k = 0; k < 8; k++) {
            float a[8], bb[8];
            *(float4*)(a)    = *(float4*)&As[k][ty*8];
            *(float4*)(a+4)  = *(float4*)&As[k][ty*8+4];
            *(float4*)(bb)   = *(float4*)&Bs[k][tx*8];
            *(float4*)(bb+4) = *(float4*)&Bs[k][tx*8+4];
            #pragma unroll
            for (int i = 0; i < 8; i++)
                #pragma unroll
                for (int j = 0; j < 8; j++) acc[i][j] += a[i]*bb[j];
        }
        __syncthreads();
    }
    #pragma unroll
    for (int i = 0; i < 8; i++) {
        float* cp = C + (size_t)(m0 + ty*8 + i)*Nn + n0 + tx*8;
        *(float4*)cp     = make_float4(acc[i][0], acc[i][1], acc[i][2], acc[i][3]);
        *(float4*)(cp+4) = make_float4(acc[i][4], acc[i][5], acc[i][6], acc[i][7]);
    }
}

// ------------------- fast exp on FMA pipe -------------------
__device__ __forceinline__ float fast_exp(float x) {
    float y = x * 1.4426950408889634f;
    if (y < -120.f) return 0.f;
    float n = rintf(y);
    float r = (y - n) * 0.6931471805599453f;
    float p = 1.f/720.f;
    p = p*r + 1.f/120.f;
    p = p*r + 1.f/24.f;
    p = p*r + 1.f/6.f;
    p = p*r + 0.5f;
    p = p*r + 1.f;
    p = p*r + 1.f;
    int e = (int)n;
    float s = __int_as_float((e + 127) << 23);
    return p * s;
}

// ------------------- attention (proven: smem scores) -------------------
__global__ void attn_kernel(int layer) {
    extern __shared__ float asm_[];
    float* ksh  = asm_;                    // [128][16]
    float* vsh  = asm_ + 2048;             // [128][16]
    float* S    = asm_ + 4096;             // [128][129]
    float* rsum = asm_ + 4096 + 128*SSTR;  // [128]

    int bh = blockIdx.x;
    int b = bh >> 3, hd = bh & 7;
    int t = threadIdx.x;                   // 256 threads
    const float* qkv = g_qkv + (size_t)b * DIMS_ * 384;

    for (int e = t; e < DIMS_*DK_; e += 256) {
        int m = e >> 4, d = e & 15;
        ksh[m*DK_ + d] = qkv[(size_t)m*384 + 128 + hd*DK_ + d];
        vsh[m*DK_ + d] = qkv[(size_t)m*384 + 256 + hd*DK_ + d];
    }
    __syncthreads();

    int q = t >> 1, half = t & 1;
    float qv[DK_];
    #pragma unroll
    for (int d = 0; d < DK_; d++) qv[d] = qkv[(size_t)q*384 + hd*DK_ + d];
    float lmax = -INFINITY;
    #pragma unroll 4
    for (int i = 0; i < 64; i++) {
        int m = half*64 + i;
        float s = 0.f;
        #pragma unroll
        for (int d = 0; d < DK_; d++) s += qv[d]*ksh[m*DK_ + d];
        s *= 0.25f;
        S[q*SSTR + m] = s;
        lmax = fmaxf(lmax, s);
    }
    float rmax = fmaxf(lmax, __shfl_xor_sync(0xffffffffu, lmax, 1));
    float lsum = 0.f;
    #pragma unroll 4
    for (int i = 0; i < 64; i++) {
        int m = half*64 + i;
        float p = fast_exp(S[q*SSTR + m] - rmax);
        S[q*SSTR + m] = p;
        lsum += p;
    }
    lsum += __shfl_xor_sync(0xffffffffu, lsum, 1);
    if (half == 0) rsum[q] = lsum;
    __syncthreads();

    int q2 = t & 127, dh = t >> 7;
    float acc[8];
    #pragma unroll
    for (int j = 0; j < 8; j++) acc[j] = 0.f;
    for (int m = 0; m < 128; m++) {
        float p = S[q2*SSTR + m];
        #pragma unroll
        for (int j = 0; j < 8; j++) acc[j] += p * vsh[m*DK_ + dh*8 + j];
    }
    float inv = 1.f / rsum[q2];
    float* ob = g_feats + (size_t)(layer*B_ + b)*DIMS_*H_ + (size_t)q2*H_ + hd*DK_ + dh*8;
    *(float4*)ob     = make_float4(acc[0]*inv, acc[1]*inv, acc[2]*inv, acc[3]*inv);
    *(float4*)(ob+4) = make_float4(acc[4]*inv, acc[5]*inv, acc[6]*inv, acc[7]*inv);
}

// ------------------- fused classifier head -------------------
__global__ void head_kernel(const float* __restrict__ Wc1, const float* __restrict__ bc1,
                            const float* __restrict__ Wc2, const float* __restrict__ bc2,
                            const float* __restrict__ Wl1, const float* __restrict__ bl1,
                            const float* __restrict__ Wl2, const float* __restrict__ bl2,
                            float* __restrict__ out)
{
    int b = blockIdx.x;
    int t = threadIdx.x;
    __shared__ float ysh[C1_][H_];
    __shared__ float ypsh[C1_][H_/2];
    __shared__ float partial[128];
    __shared__ float z0[C2_];
    __shared__ float z1s[C2_];
    __shared__ float vv[NC_];

    float acc[C1_];
    #pragma unroll
    for (int o = 0; o < C1_; o++) acc[o] = 0.f;
    for (int c = 0; c < 3; c++) {
        const float* fb = g_feats + (size_t)(c*B_ + b)*DIMS_*H_;
        for (int d = 0; d < DIMS_; d++) {
            float xv = fb[(size_t)d*H_ + t];
            int cd = c*DIMS_ + d;
            #pragma unroll
            for (int o = 0; o < C1_; o++) acc[o] += Wc1[o*384 + cd] * xv;
        }
    }
    #pragma unroll
    for (int o = 0; o < C1_; o++) ysh[o][t] = fmaxf(acc[o] + bc1[o], 0.f);
    __syncthreads();

    if (t < H_/2) {
        #pragma unroll
        for (int o = 0; o < C1_; o++)
            ypsh[o][t] = fmaxf(ysh[o][2*t], ysh[o][2*t+1]);
    }
    __syncthreads();

    {
        int o2 = t & 63, halfq = t >> 6;
        float s2 = 0.f;
        for (int c = halfq*16; c < halfq*16 + 16; c++) {
            const float* wrow = Wc2 + ((size_t)o2*C1_ + c)*64;
            #pragma unroll
            for (int w = 0; w < 64; w++) s2 += ypsh[c][w] * wrow[w];
        }
        partial[t] = s2;
    }
    __syncthreads();
    if (t < C2_) z0[t] = fmaxf(partial[t] + partial[t+64] + bc2[t], 0.f);
    __syncthreads();

    if (t < C2_) {
        float s = bl1[t];
        #pragma unroll
        for (int i = 0; i < C2_; i++) s += z0[i] * Wl1[i*C2_ + t];
        z1s[t] = fmaxf(s, 0.f);
    }
    __syncthreads();

    if (t < NC_) {
        float s = bl2[t];
        #pragma unroll
        for (int i = 0; i < C2_; i++) s += z1s[i] * Wl2[i*NC_ + t];
        vv[t] = s;
    }
    __syncthreads();

    if (t == 0) {
        float mx = vv[0];
        for (int i = 1; i < NC_; i++) mx = fmaxf(mx, vv[i]);
        float se = 0.f;
        for (int i = 0; i < NC_; i++) se += expf(vv[i] - mx);
        float ls = logf(se);
        for (int i = 0; i < NC_; i++) out[b*NC_ + i] = vv[i] - mx - ls;
    }
}

// ------------------- host driver -------------------
extern "C" void kernel_launch(void* const* d_in, const int* in_sizes, int n_in,
                              void* d_out, int out_size)
{
    const float* x   = (const float*)d_in[0];
    const int*   src = (const int*)d_in[1];
    const int*   dst = (const int*)d_in[2];
    const float* Wg[3] = {(const float*)d_in[3], (const float*)d_in[5], (const float*)d_in[7]};
    const float* bg[3] = {(const float*)d_in[4], (const float*)d_in[6], (const float*)d_in[8]};
    const float* Wp  = (const float*)d_in[9];
    const float* bp  = (const float*)d_in[10];
    const float* Wq  = (const float*)d_in[11];
    const float* Wk  = (const float*)d_in[12];
    const float* Wv  = (const float*)d_in[13];
    const float* Wc1 = (const float*)d_in[14];
    const float* bc1 = (const float*)d_in[15];
    const float* Wc2 = (const float*)d_in[16];
    const float* bc2 = (const float*)d_in[17];
    const float* Wl1 = (const float*)d_in[18];
    const float* bl1 = (const float*)d_in[19];
    const float* Wl2 = (const float*)d_in[20];
    const float* bl2 = (const float*)d_in[21];
    int E = in_sizes[1];

    ensure_streams();

    float *ph0, *ph1, *pqkv, *pfeats, *pWqkv;
    cudaGetSymbolAddress((void**)&ph0,    g_h0);
    cudaGetSymbolAddress((void**)&ph1,    g_h1);
    cudaGetSymbolAddress((void**)&pqkv,   g_qkv);
    cudaGetSymbolAddress((void**)&pfeats, g_feats);
    cudaGetSymbolAddress((void**)&pWqkv,  g_Wqkv);
    float* hbuf[2] = {ph0, ph1};

    const int LAYER_SMEM = (256*PPAD + 128*128 + 256 + 256 + 256) * (int)sizeof(float);
    const int ATTN_SMEM  = (4096 + 128*SSTR + 128) * (int)sizeof(float);
    cudaFuncSetAttribute(layer_kernel, cudaFuncAttributeMaxDynamicSharedMemorySize, LAYER_SMEM);
    cudaFuncSetAttribute(attn_kernel,  cudaFuncAttributeMaxDynamicSharedMemorySize, ATTN_SMEM);

    // ---- prep (main stream) ----
    zero_kernel<<<(NN + 255)/256, 256>>>();
    deg_kernel<<<(E + 255)/256, 256>>>(dst, E);
    scan_kernel<<<B_, NP_>>>();
    scatter_kernel<<<(E + 255)/256, 256>>>(src, dst, E, Wq, Wk, Wv);

    // ---- pipelined layers; sort+gather+qkv+attn on side stream ----
    for (int l = 0; l < 3; l++) {
        const float* hin = (l == 0) ? x : hbuf[(l + 1) & 1];
        float* hout = hbuf[l & 1];
        if (l >= 2) cudaStreamWaitEvent(0, s_evG[l - 2], 0);   // hbuf[l&1] still read by sortgather(l-2)
        layer_kernel<<<B_, 1024, LAYER_SMEM>>>(hin, Wg[l], bg[l], Wp, bp, hout, l);
        cudaEventRecord(s_evL[l], 0);
        cudaStreamWaitEvent(s_side, s_evL[l], 0);
        sortgather_kernel<<<B_, NP_, 0, s_side>>>(hout, l);
        cudaEventRecord(s_evG[l], s_side);
        const float* fl = pfeats + (size_t)l*B_*DIMS_*H_;
        gemm128<<<dim3(B_*DIMS_/128, 3), 256, 0, s_side>>>(fl, pWqkv, pqkv, B_*DIMS_, 384, H_);
        attn_kernel<<<B_*HEADS_, 256, ATTN_SMEM, s_side>>>(l);
    }

    // ---- join: head needs all three attn outputs ----
    cudaEventRecord(s_evJoin, s_side);
    cudaStreamWaitEvent(0, s_evJoin, 0);
    head_kernel<<<B_, 128>>>(Wc1, bc1, Wc2, bc2, Wl1, bl1, Wl2, bl2, (float*)d_out);
}

// round 14
// speedup vs baseline: 1.0378x; 1.0378x over previous
#include <cuda_runtime.h>
#include <math.h>

#define B_    128
#define NP_   256
#define NN    (B_*NP_)
#define H_    128
#define DIMS_ 128
#define HEADS_ 8
#define DK_   16
#define C1_   32
#define C2_   64
#define NC_   10
#define EPG   4096
#define ETOT  (B_*EPG)
#define PPAD  132
#define SSTR  129

// ------------------- device scratch -------------------
__device__ float g_deg[NN];
__device__ float g_dnorm[NN];
__device__ int   g_off[NN];
__device__ int   g_cur[NN];
__device__ unsigned short g_csr[ETOT];
__device__ float g_h[(size_t)NN*H_];
__device__ float g_feats[(size_t)3*B_*DIMS_*H_];
__device__ float g_qkv[(size_t)B_*DIMS_*384];
__device__ float g_Wqkv[(size_t)H_*384];

// ------------------- side stream + events -------------------
static cudaStream_t s_side = 0;
static cudaEvent_t  s_evL[3] = {0,0,0};
static cudaEvent_t  s_evJoin = 0;
static void ensure_streams() {
    if (!s_side) {
        cudaStreamCreateWithFlags(&s_side, cudaStreamNonBlocking);
        for (int i = 0; i < 3; i++)
            cudaEventCreateWithFlags(&s_evL[i], cudaEventDisableTiming);
        cudaEventCreateWithFlags(&s_evJoin, cudaEventDisableTiming);
    }
}
namespace { struct _StreamInit { _StreamInit() { ensure_streams(); } } _stream_init; }

// ------------------- prep -------------------
__global__ void deg_kernel(const int* __restrict__ dst, int E) {
    int e = blockIdx.x * blockDim.x + threadIdx.x;
    if (e < E) atomicAdd(&g_deg[dst[e]], 1.0f);
}
// scan: CSR offsets + dnorm + zero g_cur (runs before scatter, which uses g_cur)
__global__ void scan_kernel() {
    int g = blockIdx.x, t = threadIdx.x;
    __shared__ int a[NP_];
    int node = g*NP_ + t;
    float degf = g_deg[node];
    int v = (int)degf;
    a[t] = v;
    __syncthreads();
    for (int off = 1; off < NP_; off <<= 1) {
        int x = a[t];
        if (t >= off) x += a[t - off];
        __syncthreads();
        a[t] = x;
        __syncthreads();
    }
    g_off[node] = g*EPG + a[t] - v;
    g_dnorm[node] = rsqrtf(fmaxf(degf, 1.0f));
    g_cur[node] = 0;
}
__global__ void scatter_kernel(const int* __restrict__ src, const int* __restrict__ dst, int E,
                               const float* __restrict__ Wq, const float* __restrict__ Wk,
                               const float* __restrict__ Wv) {
    int e = blockIdx.x * blockDim.x + threadIdx.x;
    if (e < E) {
        int s = src[e], d = dst[e];
        int pos = atomicAdd(&g_cur[d], 1);
        g_csr[g_off[d] + pos] = (unsigned short)(s & 255);
    }
    if (e < H_*H_) {
        int k = e >> 7, c = e & 127;
        g_Wqkv[k*384 + c]       = Wq[e];
        g_Wqkv[k*384 + 128 + c] = Wk[e];
        g_Wqkv[k*384 + 256 + c] = Wv[e];
    }
}

// ------------------- mega-fused layer kernel: 1024 threads (round-9 proven) -------------------
__global__ void __launch_bounds__(1024, 1)
layer_kernel(const float* __restrict__ hin, const float* __restrict__ W,
             const float* __restrict__ bias, const float* __restrict__ Wp,
             const float* __restrict__ bp, float* __restrict__ hout, int layer)
{
    extern __shared__ float sm[];
    float* P    = sm;                      // [256][132]
    float* Wm   = P + 256*PPAD;            // [128][128]
    float* dn   = Wm + 128*128;            // [256]
    float* sps  = dn + 256;                // [256]
    float* ssh  = sps + 256;               // [256]
    float* v    = ssh + 256;               // [256]
    float* gate = v + 256;                 // [128]
    int*   ix   = (int*)(gate + 128);      // [256]

    int g = blockIdx.x, t = threadIdx.x;   // 1024 threads

    // ---- phase 1: stage ----
    for (int i = t; i < 128*32; i += 1024)
        ((float4*)Wm)[i] = ((const float4*)W)[i];
    if (t < 256) dn[t] = g_dnorm[g*NP_ + t];
    {
        const float4* h4 = (const float4*)(hin + (size_t)g*NP_*H_);
        for (int i = t; i < 256*32; i += 1024) {
            int r = i >> 5, c = i & 31;
            *(float4*)&P[r*PPAD + c*4] = h4[i];
        }
    }
    __syncthreads();

    // ---- phase 2: in-place GEMM pre = h @ W (1 row x 32 cols per thread) ----
    {
        int r = t & 255, cg = t >> 8;      // 256 rows x 4 col-groups
        int c0 = cg * 32;
        float acc[32];
        #pragma unroll
        for (int j = 0; j < 32; j++) acc[j] = 0.f;
        const float* arow = &P[r*PPAD];
        for (int k = 0; k < 128; k++) {
            float a = arow[k];
            const float4* wr4 = (const float4*)(Wm + k*128 + c0);
            #pragma unroll
            for (int j4 = 0; j4 < 8; j4++) {
                float4 w4 = wr4[j4];
                acc[j4*4+0] += a * w4.x;
                acc[j4*4+1] += a * w4.y;
                acc[j4*4+2] += a * w4.z;
                acc[j4*4+3] += a * w4.w;
            }
        }
        __syncthreads();   // all reads of h done before overwrite
        float sc = dn[r];
        float4* prow4 = (float4*)(P + r*PPAD + c0);
        #pragma unroll
        for (int j4 = 0; j4 < 8; j4++)
            prow4[j4] = make_float4(acc[j4*4+0]*sc, acc[j4*4+1]*sc,
                                    acc[j4*4+2]*sc, acc[j4*4+3]*sc);
    }
    __syncthreads();

    // ---- phase 3: CSR aggregation + relu + bias, fused sp projection ----
    {
        int warp = t >> 5, lane = t & 31;   // 32 warps x 8 nodes
        float4 bv = ((const float4*)bias)[lane];
        float4 wp = ((const float4*)Wp)[lane];
        for (int d0 = warp*8; d0 < warp*8 + 8; d0 += 4) {
            int beg[4], len[4];
            float4 acc[4];
            int maxlen = 0;
            #pragma unroll
            for (int j = 0; j < 4; j++) {
                int node = g*NP_ + d0 + j;
                beg[j] = g_off[node];
                len[j] = (int)g_deg[node];
                maxlen = max(maxlen, len[j]);
                acc[j] = make_float4(0.f, 0.f, 0.f, 0.f);
            }
            for (int i = 0; i < maxlen; i++) {
                #pragma unroll
                for (int j = 0; j < 4; j++) {
                    if (i < len[j]) {
                        int s = g_csr[beg[j] + i];
                        float4 vv = *(const float4*)&P[s*PPAD + lane*4];
                        acc[j].x += vv.x; acc[j].y += vv.y; acc[j].z += vv.z; acc[j].w += vv.w;
                    }
                }
            }
            #pragma unroll
            for (int j = 0; j < 4; j++) {
                int node = g*NP_ + d0 + j;
                float sc = dn[d0 + j];
                float4 o;
                o.x = fmaxf(acc[j].x*sc + bv.x, 0.f);
                o.y = fmaxf(acc[j].y*sc + bv.y, 0.f);
                o.z = fmaxf(acc[j].z*sc + bv.z, 0.f);
                o.w = fmaxf(acc[j].w*sc + bv.w, 0.f);
                ((float4*)hout)[(size_t)node*32 + lane] = o;
                float s = o.x*wp.x + o.y*wp.y + o.z*wp.z + o.w*wp.w;
                #pragma unroll
                for (int off = 16; off; off >>= 1) s += __shfl_down_sync(0xffffffffu, s, off);
                if (lane == 0) sps[d0 + j] = s;
            }
        }
    }
    __syncthreads();

    // ---- phase 4: score via CSR ----
    if (t < 256) ssh[t] = sps[t] * dn[t];
    __syncthreads();
    if (t < 256) {
        int node = g*NP_ + t;
        int beg = g_off[node], len = (int)g_deg[node];
        float s = 0.f;
        for (int i = 0; i < len; i++) s += ssh[g_csr[beg + i]];
        v[t]  = s * dn[t] + bp[0];
        ix[t] = t;
    }
    __syncthreads();

    // ---- phase 5: bitonic sort (desc value, asc index) ----
    for (int k = 2; k <= NP_; k <<= 1) {
        for (int j = k >> 1; j > 0; j >>= 1) {
            if (t < 256) {
                int p = t ^ j;
                if (p > t) {
                    bool dirDesc = ((t & k) == 0);
                    float v1 = v[t], v2 = v[p];
                    int i1 = ix[t], i2 = ix[p];
                    bool a_gt = (v1 > v2) || (v1 == v2 && i1 < i2);
                    if (dirDesc != a_gt) {
                        v[t] = v2; v[p] = v1; ix[t] = i2; ix[p] = i1;
                    }
                }
            }
            __syncthreads();
        }
    }
    if (t < 128) gate[t] = tanhf(v[t]);
    __syncthreads();

    // ---- phase 6: gather + gate -> feats ----
    float* dstp = g_feats + (size_t)(layer*B_ + g)*DIMS_*H_;
    for (int e = t; e < DIMS_*H_; e += 1024) {
        int j = e >> 7, c = e & 127;
        dstp[e] = hout[((size_t)g*NP_ + ix[j])*H_ + c] * gate[j];
    }
}

// ------------------- fp32 SGEMM (QKV): 128x128 tile, 8x8/thread -------------------
__global__ void gemm128(const float* __restrict__ A, const float* __restrict__ B,
                        float* __restrict__ C, int M, int Nn, int K)
{
    __shared__ float As[8][128];
    __shared__ float Bs[8][128];
    int t = threadIdx.x;
    int m0 = blockIdx.x * 128, n0 = blockIdx.y * 128;
    int tx = t & 15, ty = t >> 4;
    int arow = t >> 1, aseg = t & 1;
    int brow = t >> 5, bcol = t & 31;
    float acc[8][8];
    #pragma unroll
    for (int i = 0; i < 8; i++)
        #pragma unroll
        for (int j = 0; j < 8; j++) acc[i][j] = 0.f;

    for (int k0 = 0; k0 < K; k0 += 8) {
        float4 av  = *(const float4*)(A + (size_t)(m0 + arow)*K + k0 + aseg*4);
        float4 bvv = *(const float4*)(B + (size_t)(k0 + brow)*Nn + n0 + bcol*4);
        As[aseg*4+0][arow] = av.x;
        As[aseg*4+1][arow] = av.y;
        As[aseg*4+2][arow] = av.z;
        As[aseg*4+3][arow] = av.w;
        *(float4*)&Bs[brow][bcol*4] = bvv;
        __syncthreads();
        #pragma unroll
        for (int k = 0; k < 8; k++) {
            float a[8], bb[8];
            *(float4*)(a)    = *(float4*)&As[k][ty*8];
            *(float4*)(a+4)  = *(float4*)&As[k][ty*8+4];
            *(float4*)(bb)   = *(float4*)&Bs[k][tx*8];
            *(float4*)(bb+4) = *(float4*)&Bs[k][tx*8+4];
            #pragma unroll
            for (int i = 0; i < 8; i++)
                #pragma unroll
                for (int j = 0; j < 8; j++) acc[i][j] += a[i]*bb[j];
        }
        __syncthreads();
    }
    #pragma unroll
    for (int i = 0; i < 8; i++) {
        float* cp = C + (size_t)(m0 + ty*8 + i)*Nn + n0 + tx*8;
        *(float4*)cp     = make_float4(acc[i][0], acc[i][1], acc[i][2], acc[i][3]);
        *(float4*)(cp+4) = make_float4(acc[i][4], acc[i][5], acc[i][6], acc[i][7]);
    }
}

// ------------------- fast exp on FMA pipe -------------------
__device__ __forceinline__ float fast_exp(float x) {
    float y = x * 1.4426950408889634f;
    if (y < -120.f) return 0.f;
    float n = rintf(y);
    float r = (y - n) * 0.6931471805599453f;
    float p = 1.f/720.f;
    p = p*r + 1.f/120.f;
    p = p*r + 1.f/24.f;
    p = p*r + 1.f/6.f;
    p = p*r + 0.5f;
    p = p*r + 1.f;
    p = p*r + 1.f;
    int e = (int)n;
    float s = __int_as_float((e + 127) << 23);
    return p * s;
}

// ------------------- attention (proven: smem scores) -------------------
__global__ void attn_kernel(int layer) {
    extern __shared__ float asm_[];
    float* ksh  = asm_;                    // [128][16]
    float* vsh  = asm_ + 2048;             // [128][16]
    float* S    = asm_ + 4096;             // [128][129]
    float* rsum = asm_ + 4096 + 128*SSTR;  // [128]

    int bh = blockIdx.x;
    int b = bh >> 3, hd = bh & 7;
    int t = threadIdx.x;                   // 256 threads
    const float* qkv = g_qkv + (size_t)b * DIMS_ * 384;

    for (int e = t; e < DIMS_*DK_; e += 256) {
        int m = e >> 4, d = e & 15;
        ksh[m*DK_ + d] = qkv[(size_t)m*384 + 128 + hd*DK_ + d];
        vsh[m*DK_ + d] = qkv[(size_t)m*384 + 256 + hd*DK_ + d];
    }
    __syncthreads();

    int q = t >> 1, half = t & 1;
    float qv[DK_];
    #pragma unroll
    for (int d = 0; d < DK_; d++) qv[d] = qkv[(size_t)q*384 + hd*DK_ + d];
    float lmax = -INFINITY;
    #pragma unroll 4
    for (int i = 0; i < 64; i++) {
        int m = half*64 + i;
        float s = 0.f;
        #pragma unroll
        for (int d = 0; d < DK_; d++) s += qv[d]*ksh[m*DK_ + d];
        s *= 0.25f;
        S[q*SSTR + m] = s;
        lmax = fmaxf(lmax, s);
    }
    float rmax = fmaxf(lmax, __shfl_xor_sync(0xffffffffu, lmax, 1));
    float lsum = 0.f;
    #pragma unroll 4
    for (int i = 0; i < 64; i++) {
        int m = half*64 + i;
        float p = fast_exp(S[q*SSTR + m] - rmax);
        S[q*SSTR + m] = p;
        lsum += p;
    }
    lsum += __shfl_xor_sync(0xffffffffu, lsum, 1);
    if (half == 0) rsum[q] = lsum;
    __syncthreads();

    int q2 = t & 127, dh = t >> 7;
    float acc[8];
    #pragma unroll
    for (int j = 0; j < 8; j++) acc[j] = 0.f;
    for (int m = 0; m < 128; m++) {
        float p = S[q2*SSTR + m];
        #pragma unroll
        for (int j = 0; j < 8; j++) acc[j] += p * vsh[m*DK_ + dh*8 + j];
    }
    float inv = 1.f / rsum[q2];
    float* ob = g_feats + (size_t)(layer*B_ + b)*DIMS_*H_ + (size_t)q2*H_ + hd*DK_ + dh*8;
    *(float4*)ob     = make_float4(acc[0]*inv, acc[1]*inv, acc[2]*inv, acc[3]*inv);
    *(float4*)(ob+4) = make_float4(acc[4]*inv, acc[5]*inv, acc[6]*inv, acc[7]*inv);
}

// ------------------- fused classifier head -------------------
__global__ void head_kernel(const float* __restrict__ Wc1, const float* __restrict__ bc1,
                            const float* __restrict__ Wc2, const float* __restrict__ bc2,
                            const float* __restrict__ Wl1, const float* __restrict__ bl1,
                            const float* __restrict__ Wl2, const float* __restrict__ bl2,
                            float* __restrict__ out)
{
    int b = blockIdx.x;
    int t = threadIdx.x;
    __shared__ float ysh[C1_][H_];
    __shared__ float ypsh[C1_][H_/2];
    __shared__ float partial[128];
    __shared__ float z0[C2_];
    __shared__ float z1s[C2_];
    __shared__ float vv[NC_];

    float acc[C1_];
    #pragma unroll
    for (int o = 0; o < C1_; o++) acc[o] = 0.f;
    for (int c = 0; c < 3; c++) {
        const float* fb = g_feats + (size_t)(c*B_ + b)*DIMS_*H_;
        for (int d = 0; d < DIMS_; d++) {
            float xv = fb[(size_t)d*H_ + t];
            int cd = c*DIMS_ + d;
            #pragma unroll
            for (int o = 0; o < C1_; o++) acc[o] += Wc1[o*384 + cd] * xv;
        }
    }
    #pragma unroll
    for (int o = 0; o < C1_; o++) ysh[o][t] = fmaxf(acc[o] + bc1[o], 0.f);
    __syncthreads();

    if (t < H_/2) {
        #pragma unroll
        for (int o = 0; o < C1_; o++)
            ypsh[o][t] = fmaxf(ysh[o][2*t], ysh[o][2*t+1]);
    }
    __syncthreads();

    {
        int o2 = t & 63, halfq = t >> 6;
        float s2 = 0.f;
        for (int c = halfq*16; c < halfq*16 + 16; c++) {
            const float* wrow = Wc2 + ((size_t)o2*C1_ + c)*64;
            #pragma unroll
            for (int w = 0; w < 64; w++) s2 += ypsh[c][w] * wrow[w];
        }
        partial[t] = s2;
    }
    __syncthreads();
    if (t < C2_) z0[t] = fmaxf(partial[t] + partial[t+64] + bc2[t], 0.f);
    __syncthreads();

    if (t < C2_) {
        float s = bl1[t];
        #pragma unroll
        for (int i = 0; i < C2_; i++) s += z0[i] * Wl1[i*C2_ + t];
        z1s[t] = fmaxf(s, 0.f);
    }
    __syncthreads();

    if (t < NC_) {
        float s = bl2[t];
        #pragma unroll
        for (int i = 0; i < C2_; i++) s += z1s[i] * Wl2[i*NC_ + t];
        vv[t] = s;
    }
    __syncthreads();

    if (t == 0) {
        float mx = vv[0];
        for (int i = 1; i < NC_; i++) mx = fmaxf(mx, vv[i]);
        float se = 0.f;
        for (int i = 0; i < NC_; i++) se += expf(vv[i] - mx);
        float ls = logf(se);
        for (int i = 0; i < NC_; i++) out[b*NC_ + i] = vv[i] - mx - ls;
    }
}

// ------------------- host driver -------------------
extern "C" void kernel_launch(void* const* d_in, const int* in_sizes, int n_in,
                              void* d_out, int out_size)
{
    const float* x   = (const float*)d_in[0];
    const int*   src = (const int*)d_in[1];
    const int*   dst = (const int*)d_in[2];
    const float* Wg[3] = {(const float*)d_in[3], (const float*)d_in[5], (const float*)d_in[7]};
    const float* bg[3] = {(const float*)d_in[4], (const float*)d_in[6], (const float*)d_in[8]};
    const float* Wp  = (const float*)d_in[9];
    const float* bp  = (const float*)d_in[10];
    const float* Wq  = (const float*)d_in[11];
    const float* Wk  = (const float*)d_in[12];
    const float* Wv  = (const float*)d_in[13];
    const float* Wc1 = (const float*)d_in[14];
    const float* bc1 = (const float*)d_in[15];
    const float* Wc2 = (const float*)d_in[16];
    const float* bc2 = (const float*)d_in[17];
    const float* Wl1 = (const float*)d_in[18];
    const float* bl1 = (const float*)d_in[19];
    const float* Wl2 = (const float*)d_in[20];
    const float* bl2 = (const float*)d_in[21];
    int E = in_sizes[1];

    ensure_streams();

    float *pdeg, *ph, *pqkv, *pfeats, *pWqkv;
    cudaGetSymbolAddress((void**)&pdeg,   g_deg);
    cudaGetSymbolAddress((void**)&ph,     g_h);
    cudaGetSymbolAddress((void**)&pqkv,   g_qkv);
    cudaGetSymbolAddress((void**)&pfeats, g_feats);
    cudaGetSymbolAddress((void**)&pWqkv,  g_Wqkv);

    const int LAYER_SMEM = (256*PPAD + 128*128 + 256 + 256 + 256 + 256 + 128 + 256) * (int)sizeof(float);
    const int ATTN_SMEM  = (4096 + 128*SSTR + 128) * (int)sizeof(float);
    cudaFuncSetAttribute(layer_kernel, cudaFuncAttributeMaxDynamicSharedMemorySize, LAYER_SMEM);
    cudaFuncSetAttribute(attn_kernel,  cudaFuncAttributeMaxDynamicSharedMemorySize, ATTN_SMEM);

    // ---- prep (main stream); zeroing via memset NODE (not a kernel launch) ----
    cudaMemsetAsync(pdeg, 0, NN * sizeof(float), 0);
    deg_kernel<<<(E + 255)/256, 256>>>(dst, E);
    scan_kernel<<<B_, NP_>>>();                 // also zeroes g_cur before scatter
    scatter_kernel<<<(E + 255)/256, 256>>>(src, dst, E, Wq, Wk, Wv);

    // ---- pipelined layers: layer(l+1) overlaps qkv+attn(l) on side stream ----
    for (int l = 0; l < 3; l++) {
        const float* hin = (l == 0) ? x : ph;
        layer_kernel<<<B_, 1024, LAYER_SMEM>>>(hin, Wg[l], bg[l], Wp, bp, ph, l);
        cudaEventRecord(s_evL[l], 0);
        cudaStreamWaitEvent(s_side, s_evL[l], 0);
        const float* fl = pfeats + (size_t)l*B_*DIMS_*H_;
        gemm128<<<dim3(B_*DIMS_/128, 3), 256, 0, s_side>>>(fl, pWqkv, pqkv, B_*DIMS_, 384, H_);
        attn_kernel<<<B_*HEADS_, 256, ATTN_SMEM, s_side>>>(l);
    }

    // ---- join: head needs all three attn outputs ----
    cudaEventRecord(s_evJoin, s_side);
    cudaStreamWaitEvent(0, s_evJoin, 0);
    head_kernel<<<B_, 128>>>(Wc1, bc1, Wc2, bc2, Wl1, bl1, Wl2, bl2, (float*)d_out);
}